// round 9
// baseline (speedup 1.0000x reference)
#include <cuda_runtime.h>

// Depthwise 3x3 conv with one-hot (hard-softmax) weight == pure spatial shift:
//   out[b,c,h,w] = x[b,c,h+dh,w+dw]  (zero outside), (dh,dw) = abs-argmax of
// the 9 weights (first max wins, matching jnp.argmax).
// Shapes fixed: B=16, C=64, H=256, W=256 fp32.
//
// Converged configuration (best of 8 measured variants, ~75.6us kernel,
// ~6.35 TB/s combined R+W ~ the practical HBM streaming ceiling):
//  - 2 warp-interleaved float4 streams per thread (MLP=2; >2 measured neutral)
//  - dw=+-1 path: 4x LDG.32 at 16B lane stride (measured FASTER than
//    LDG.128+scalar and than shuffle assembly)
//  - plain stores (streaming hints neutral-to-negative), flat 32768-block grid
// R9 delta: argmax per-WARP (lane 0 + shfl broadcast) instead of per-block
// thread0 + __syncthreads -> no block barrier in the prologue.

#define H_DIM 256
#define W_DIM 256

__device__ __forceinline__ float4
load_shifted(const float* __restrict__ x, int v, int dh, int dw) {
    // v = float4 output index. W=256 -> 64 float4/row.
    const int w4 = v & 63;
    const int h  = (v >> 6) & 255;
    const int bc = v >> 14;

    float4 val = make_float4(0.f, 0.f, 0.f, 0.f);
    const int hi = h + dh;
    if ((unsigned)hi < (unsigned)H_DIM) {
        const float* __restrict__ row = x + ((long long)bc * H_DIM + hi) * W_DIM;
        if (dw == 0) {
            val = __ldg(reinterpret_cast<const float4*>(row) + w4);
        } else {
            // Lane addresses stride 16B across the warp -> well coalesced.
            const int wa = (w4 << 2) + dw;
            val.x = ((unsigned)wa       < (unsigned)W_DIM) ? __ldg(row + wa)     : 0.f;
            val.y = ((unsigned)(wa + 1) < (unsigned)W_DIM) ? __ldg(row + wa + 1) : 0.f;
            val.z = ((unsigned)(wa + 2) < (unsigned)W_DIM) ? __ldg(row + wa + 2) : 0.f;
            val.w = ((unsigned)(wa + 3) < (unsigned)W_DIM) ? __ldg(row + wa + 3) : 0.f;
        }
    }
    return val;
}

__global__ void __launch_bounds__(256)
shift_fused2w_kernel(const float* __restrict__ x, const float* __restrict__ wt,
                     float* __restrict__ out) {
    // Per-warp argmax: lane 0 loads the 9 weights (L1/L2 hits after the first
    // blocks) and broadcasts packed (dh+1, dw+1) via one shuffle. No block
    // barrier, no shared memory.
    int packed = 0;
    if ((threadIdx.x & 31) == 0) {
        float best = -1.0f;
        int bi = 0;
#pragma unroll
        for (int i = 0; i < 9; ++i) {
            float a = fabsf(__ldg(wt + i));
            if (a > best) { best = a; bi = i; }  // strict > : first max wins
        }
        packed = bi;
    }
    packed = __shfl_sync(0xffffffffu, packed, 0);
    const int dh = packed / 3 - 1;
    const int dw = packed % 3 - 1;

    // Block covers 512 consecutive float4s; thread t handles t and t+256.
    const int base = blockIdx.x * 512;
    const int v0 = base + threadIdx.x;
    const int v1 = v0 + 256;

    // Two independent load chains (front-batched by the compiler -> MLP 2).
    float4 a = load_shifted(x, v0, dh, dw);
    float4 b = load_shifted(x, v1, dh, dw);

    float4* __restrict__ o4 = reinterpret_cast<float4*>(out);
    o4[v0] = a;
    o4[v1] = b;
}

extern "C" void kernel_launch(void* const* d_in, const int* in_sizes, int n_in,
                              void* d_out, int out_size) {
    const float* x  = (const float*)d_in[0];
    const float* wt = (const float*)d_in[1];
    float* out = (float*)d_out;

    const int n4 = out_size >> 2;          // 16,777,216 float4
    const int blocks = n4 / 512;           // 32768 blocks, 256 threads, 2 f4/thread
    shift_fused2w_kernel<<<blocks, 256>>>(x, wt, out);
}